// round 10
// baseline (speedup 1.0000x reference)
#include <cuda_runtime.h>
#include <cuda_bf16.h>

#define NMASKS 128
#define W      1024
#define STRIP_ROWS 32
#define STRIPS_PER_MASK (W / STRIP_ROWS)      // 32
#define NSTRIPS (NMASKS * STRIPS_PER_MASK)    // 4096 warps
#define NBLOCKS (NSTRIPS / 8)                 // 512 blocks x 8 warps

__device__ unsigned g_mA[NMASKS];             // zero-init; reset by last warp
__device__ unsigned g_mC[NMASKS];
__device__ unsigned g_mP[NMASKS];
__device__ unsigned g_done = 0;               // atomicInc wrap -> self-resetting

struct PRow { unsigned w, lw, rw; };

__device__ __forceinline__ void csa(unsigned a, unsigned b, unsigned c,
                                    unsigned &s, unsigned &cy) {
    unsigned t = a ^ b;
    s  = t ^ c;
    cy = (a & b) | (t & c);
}

// 8 streaming LDG.128 for one full 1024-col row (coalesced)
__device__ __forceinline__ void load_row(float4 v[8], const float4* __restrict__ rb,
                                         int row, int lane) {
    const float4* __restrict__ p = rb + (size_t)row * (W / 4) + lane;
    #pragma unroll
    for (int it = 0; it < 8; it++) v[it] = __ldcs(p + it * 32);
}

// Interleaved-bitplane pack. Lane l owns word l = plane (l&3) of group (l>>2).
// Selection is a 3-level tree + masked OR into TWO partials -> ~25cyc critical
// path (was a 32-deep SEL chain in the previous version).
__device__ __forceinline__ PRow pack_row(const float4 v[8], int lane) {
    const int k   = lane & 3;
    const int grp = lane >> 2;
    unsigned wd0 = 0u, wd1 = 0u;
    #pragma unroll
    for (int it = 0; it < 8; it++) {
        unsigned b0 = __ballot_sync(0xffffffffu, v[it].x > 0.0f);
        unsigned b1 = __ballot_sync(0xffffffffu, v[it].y > 0.0f);
        unsigned b2 = __ballot_sync(0xffffffffu, v[it].z > 0.0f);
        unsigned b3 = __ballot_sync(0xffffffffu, v[it].w > 0.0f);
        unsigned s01 = (k & 1) ? b1 : b0;
        unsigned s23 = (k & 1) ? b3 : b2;
        unsigned bsel = (k & 2) ? s23 : s01;
        unsigned m = (grp == it) ? 0xffffffffu : 0u;   // per-lane constant
        if (it < 4) wd0 |= bsel & m; else wd1 |= bsel & m;
    }
    unsigned wd = wd0 | wd1;

    unsigned l1 = __shfl_sync(0xffffffffu, wd, lane - 1);
    unsigned r1 = __shfl_sync(0xffffffffu, wd, lane + 1);
    unsigned l3 = __shfl_sync(0xffffffffu, wd, lane + 3);  // plane3 same group (k==0)
    unsigned r3 = __shfl_sync(0xffffffffu, wd, lane - 3);  // plane0 same group (k==3)
    if (lane == 0)  l1 = 0u;   // group -1 guard
    if (lane == 31) r1 = 0u;   // group  8 guard
    PRow pr;
    pr.w  = wd;
    pr.lw = (k == 0) ? ((l3 << 1) | (l1 >> 31)) : l1;
    pr.rw = (k == 3) ? ((r3 >> 1) | (r1 << 31)) : r1;
    return pr;
}

__device__ __forceinline__ void compute_row(const PRow &A, const PRow &B, const PRow &C,
                                            unsigned &accA, unsigned &accC, unsigned &accP) {
    unsigned tl = A.lw, tt = A.w,  tr = A.rw;
    unsigned ml = B.lw, mid = B.w, mr = B.rw;
    unsigned bl = C.lw, bot = C.w, br = C.rw;

    // CSA tree: per-bit 3x3-ring neighbor count (0..8) as bitplanes b0..b3
    unsigned s1, c1, s2, c2, s3, c3;
    csa(tl, tt, tr, s1, c1);
    csa(ml, mr, bl, s2, c2);
    csa(bot, br, s1, s3, c3);
    unsigned s4 = s2 ^ s3, c4 = s2 & s3;
    unsigned u1, v1;
    csa(c1, c2, c3, u1, v1);
    unsigned u2 = u1 ^ c4, v2 = u1 & c4;
    unsigned b0 = s4, b1 = u2, b2 = v1 ^ v2, b3 = v1 & v2;

    accA += __popc(mid);

    unsigned conn = __popc(b0 & mid) + 2u * __popc(b1 & mid)
                  + 4u * __popc(b2 & mid) + 8u * __popc(b3 & mid);
    unsigned tot  = __popc(b0) + 2u * __popc(b1)
                  + 4u * __popc(b2) + 8u * __popc(b3);
    unsigned perim = (tot - conn)
                   + 4u * __popc(b3 & mid)
                   + 2u * __popc(b2 & b1 & mid)
                   +      __popc(b2 & b0 & mid);
    accC += conn;
    accP += perim;
}

__global__ __launch_bounds__(256, 4)
void prior_kernel(const float* __restrict__ masks, float* __restrict__ out) {
    const int tid  = threadIdx.x;
    const int lane = tid & 31;
    const int wid  = blockIdx.x * 8 + (tid >> 5);   // global warp id == strip id

    const int mask = wid >> 5;                      // 32 strips per mask
    const int s0   = (wid & 31) * STRIP_ROWS;       // 0..992
    const float4* __restrict__ rb =
        (const float4*)masks + (size_t)mask * (size_t)(W * W / 4);

    float4 v[8];
    PRow A, B, C;

    // ---- prologue: pack rows s0-1, s0; issue loads for row s0+1 ----
    if (s0 > 0) { load_row(v, rb, s0 - 1, lane); A = pack_row(v, lane); }
    else        { A.w = 0u; A.lw = 0u; A.rw = 0u; }
    load_row(v, rb, s0, lane);
    B = pack_row(v, lane);
    load_row(v, rb, s0 + 1, lane);                  // s0+1 <= 993, always valid

    unsigned accA = 0, accC = 0, accP = 0;

    // ---- barrier-free rolling loop: v refilled right after ballots drain it ----
    #pragma unroll 1
    for (int i = 0; i < STRIP_ROWS; i++) {
        const int rC = s0 + i + 1;                  // row entering as C
        if (rC < W) {
            C = pack_row(v, lane);
            if (i < STRIP_ROWS - 1 && rC + 1 < W)
                load_row(v, rb, rC + 1, lane);      // next C, 4KB in flight
        } else {
            C.w = 0u; C.lw = 0u; C.rw = 0u;         // bottom image edge
        }
        compute_row(A, B, C, accA, accC, accP);     // center row s0+i
        A = B; B = C;
    }

    // ---- per-strip reduction: warp reduce + 3 REDG ----
    accA = __reduce_add_sync(0xffffffffu, accA);
    accC = __reduce_add_sync(0xffffffffu, accC);
    accP = __reduce_add_sync(0xffffffffu, accP);

    unsigned done = 0;
    if (lane == 0) {
        atomicAdd(&g_mA[mask], accA);
        atomicAdd(&g_mC[mask], accC);
        atomicAdd(&g_mP[mask], accP);
        __threadfence();
        done = atomicInc(&g_done, NSTRIPS - 1);     // wraps to 0 -> replayable
    }
    done = __shfl_sync(0xffffffffu, done, 0);

    // ---- last warp: score all masks (4 per lane) + reset for graph replay ----
    if (done == NSTRIPS - 1) {
        #pragma unroll
        for (int j = 0; j < 4; j++) {
            int m = lane + j * 32;
            unsigned a = *(volatile unsigned*)&g_mA[m];
            unsigned c = *(volatile unsigned*)&g_mC[m];
            unsigned p = *(volatile unsigned*)&g_mP[m];

            float area  = (float)a;
            float conn  = (float)c;
            float perim = (float)p;

            float safe_area  = (area > 0.0f) ? area : 1.0f;
            float area_ratio = area / (float)(W * W);
            float area_score = (area_ratio >= 0.001f && area_ratio <= 0.5f) ? 1.0f : 0.1f;

            float comp_score = (conn > 0.0f)
                ? fminf(1.0f, 10.0f / (conn / safe_area + 1e-6f))
                : 0.1f;

            float par = perim / safe_area;
            float shape_score = (area > 0.0f)
                ? ((par <= 100.0f) ? 1.0f : fmaxf(0.1f, 100.0f / (par + 1e-6f)))
                : 0.1f;

            float validity = 0.4f * area_score + 0.3f * comp_score + 0.3f * shape_score;
            out[m] = fmaxf(0.05f, validity);

            g_mA[m] = 0u; g_mC[m] = 0u; g_mP[m] = 0u;
        }
    }
}

extern "C" void kernel_launch(void* const* d_in, const int* in_sizes, int n_in,
                              void* d_out, int out_size) {
    const float* masks = (const float*)d_in[0];
    float* out = (float*)d_out;
    (void)in_sizes; (void)n_in; (void)out_size;

    prior_kernel<<<NBLOCKS, 256>>>(masks, out);
}